// round 14
// baseline (speedup 1.0000x reference)
#include <cuda_runtime.h>
#include <cuda_fp16.h>
#include <cstdint>

#define C_CH     64
#define NIN      2144
#define NINP     2176        // padded to 17*128
#define OUT_CH   256
#define HW       4096
#define KC       128
#define NCHUNK   17
#define PX_CTA   64
#define NTH      256

// ---------------- prep storage (device globals) ----------------
// W in MMA fragment order: [chunk 17][wn 4][sl 8][nt 4][lane 32] x uint4.
__device__ __align__(16) unsigned char g_wf[NCHUNK * 65536];
__device__ __align__(16) uchar2 g_pairs[NINP];   // {i, j}; j==64 => constant-1 channel

// ---------------- smem layout (dynamic) ----------------
// XS : x tile [65 ch][64 px] fp32 (row 64 = 1.0f)  = 16640 B
// Y  : 2 stages x [64 px][256 B] fp16 swizzled     = 2 x 16384 B
// PS : pair table 2176 uchar2                      =  4352 B
// Epilogue reuses [0, 18432) as fp32 [64][72] buffer.
#define SM_XS    0
#define SM_Y     16640
#define Y_STAGE  16384
#define SM_PS    49408
#define SM_TOT   53760

// ---------------- asm helpers ----------------
__device__ __forceinline__ void ldsm4(uint32_t (&r)[4], uint32_t addr) {
    asm volatile("ldmatrix.sync.aligned.m8n8.x4.shared.b16 {%0,%1,%2,%3}, [%4];"
                 : "=r"(r[0]), "=r"(r[1]), "=r"(r[2]), "=r"(r[3]) : "r"(addr));
}
__device__ __forceinline__ void mma16816(float (&c)[4], const uint32_t (&a)[4],
                                         uint32_t b0, uint32_t b1) {
    asm volatile(
        "mma.sync.aligned.m16n8k16.row.col.f32.f16.f16.f32 "
        "{%0,%1,%2,%3}, {%4,%5,%6,%7}, {%8,%9}, {%0,%1,%2,%3};"
        : "+f"(c[0]), "+f"(c[1]), "+f"(c[2]), "+f"(c[3])
        : "r"(a[0]), "r"(a[1]), "r"(a[2]), "r"(a[3]), "r"(b0), "r"(b1));
}

// ---------------- prep kernel (pairs + W -> fragment order) ----------------
// grid 272 x 256: one warp per (c, wn, sl, nt) tuple (2176 tuples).
__global__ void w_prep_kernel(const float* __restrict__ w) {
    const int t = threadIdx.x;
    const int l = t & 31;

    if (blockIdx.x == 0) {           // pair table
        if (t < C_CH) {
            int i = t;
            g_pairs[i] = make_uchar2((unsigned char)i, 64);
            int base = C_CH + C_CH * i - (i * (i - 1)) / 2;
            for (int j = i; j < C_CH; j++)
                g_pairs[base + (j - i)] = make_uchar2((unsigned char)i, (unsigned char)j);
        }
        if (t >= 64 && t < 96)       // padding pairs (W is zero there)
            g_pairs[NIN + (t - 64)] = make_uchar2(0, 64);
    }

    const int wq = blockIdx.x * 8 + (t >> 5);    // 0..2175
    const int nt = wq & 3;
    const int sl = (wq >> 2) & 7;
    const int wn = (wq >> 5) & 3;
    const int c  = wq >> 7;
    const int n  = wn * 64 + nt * 16 + (l >> 2);
    const int k  = c * KC + sl * 16 + 2 * (l & 3);

    const float* wr  = w + (size_t)n * NIN;
    const float* wr8 = w + (size_t)(n + 8) * NIN;
    auto V = [&](const float* row, int kk) -> float {
        return (kk < NIN) ? row[kk] : 0.0f;
    };
    __half2 h0 = __floats2half2_rn(V(wr,  k),     V(wr,  k + 1));
    __half2 h1 = __floats2half2_rn(V(wr,  k + 8), V(wr,  k + 9));
    __half2 h2 = __floats2half2_rn(V(wr8, k),     V(wr8, k + 1));
    __half2 h3 = __floats2half2_rn(V(wr8, k + 8), V(wr8, k + 9));
    uint4 val = make_uint4(*(uint32_t*)&h0, *(uint32_t*)&h1,
                           *(uint32_t*)&h2, *(uint32_t*)&h3);
    *(uint4*)(g_wf + (size_t)wq * 512 + l * 16) = val;
}

// ---------------- main kernel ----------------
__global__ __launch_bounds__(NTH, 2)
void quad_hmma_kernel(const float* __restrict__ x, float* __restrict__ out) {
    extern __shared__ __align__(1024) unsigned char smem[];
    const int tid  = threadIdx.x;
    const int wid  = tid >> 5;
    const int lane = tid & 31;
    const int wm   = wid >> 2;          // warp row (M): 0..1, 32 px each (phase id)
    const int wn   = wid & 3;           // warp col (N): 0..3, 64 ch each
    const uint32_t sb = (uint32_t)__cvta_generic_to_shared(smem);

    float*  xs = (float*)(smem + SM_XS);
    uchar2* ps = (uchar2*)(smem + SM_PS);

    // ---- global pixel tile ----
    const int p0  = blockIdx.x * PX_CTA;
    const int b   = p0 >> 12;
    const int hw0 = p0 & 4095;
    const float* xb = x + (((size_t)b * C_CH) << 12) + hw0;

    // ---- load x tile: 64 ch x 64 px (1024 float4, 4/thread) + ones row ----
    #pragma unroll
    for (int t = 0; t < 4; t++) {
        int e  = tid + t * NTH;          // 0..1023
        int ch = e >> 4;                 // 16 float4 per 64-px row
        int po = (e & 15) << 2;
        *(float4*)(xs + ch * 64 + po) = *(const float4*)(xb + ((size_t)ch << 12) + po);
    }
    if (tid < 16) *(float4*)(xs + 64 * 64 + tid * 4) = make_float4(1.f, 1.f, 1.f, 1.f);
    #pragma unroll
    for (int t = 0; t < 2; t++) {
        int idx = tid + t * NTH;
        if (idx < NINP / 8) ((uint4*)ps)[idx] = ((const uint4*)g_pairs)[idx];
    }
    __syncthreads();

    // ---- per-lane A ldmatrix bases (256-B Y rows, swizzle unit^(row&7)) ----
    const uint32_t l7    = lane & 7;
    const uint32_t aRow  = (uint32_t)(wm * 32 + (lane & 15)) * 256;
    const uint32_t aHalf = (uint32_t)(lane >> 4);

    float acc[2][8][4];
    #pragma unroll
    for (int mt = 0; mt < 2; mt++)
        #pragma unroll
        for (int j = 0; j < 8; j++)
            #pragma unroll
            for (int q = 0; q < 4; q++) acc[mt][j][q] = 0.0f;

    const int pY  = tid & 63;           // pixel this thread builds
    const int q16 = tid >> 6;           // which 16-k subgroup (0..3)
    const float* xcol = xs + pY;

    // ---- build Y: load phase (16 pairs -> 8 packed half2); round r of chunk cc ----
    auto buildLoad = [&](int cc, int r, uint32_t* yv) {
        const uint4* pp = (const uint4*)((const unsigned char*)ps
                                         + cc * 256 + r * 128 + q16 * 32);
        uint4 P0 = pp[0], P1 = pp[1];
        uint32_t wsrc[8] = {P0.x, P0.y, P0.z, P0.w, P1.x, P1.y, P1.z, P1.w};
        #pragma unroll
        for (int q = 0; q < 8; q++) {
            uint32_t w_ = wsrc[q];
            float a0 = xcol[(w_ & 255u) << 6];
            float b0 = xcol[((w_ >> 8) & 255u) << 6];
            float a1 = xcol[((w_ >> 16) & 255u) << 6];
            float b1 = xcol[(w_ >> 24) << 6];
            __half2 h = __float22half2_rn(make_float2(a0 * b0, a1 * b1));
            yv[q] = *(uint32_t*)&h;
        }
    };
    // ---- build Y: store phase (2 x STS.128, unit^(px&7) swizzle) ----
    auto buildStore = [&](int stage, int r, const uint32_t* yv) {
        unsigned char* yb = smem + SM_Y + stage * Y_STAGE + pY * 256;
        uint32_t u0 = (uint32_t)(r * 8 + q16 * 2);
        *(uint4*)(yb + ((u0 ^ (pY & 7)) << 4))       = make_uint4(yv[0], yv[1], yv[2], yv[3]);
        *(uint4*)(yb + (((u0 + 1) ^ (pY & 7)) << 4)) = make_uint4(yv[4], yv[5], yv[6], yv[7]);
    };

    // ---- prologue: build Y chunk 0 into stage 0 ----
    {
        uint32_t yv0[8];
        buildLoad(0, 0, yv0); buildStore(0, 0, yv0);
        buildLoad(0, 1, yv0); buildStore(0, 1, yv0);
    }
    __syncthreads();

    uint32_t aF[2][4], bF[4][4], yv[8];

#define LDA(sl) { _Pragma("unroll") for (int mt = 0; mt < 2; mt++) \
    ldsm4(aF[mt], ycur + aRow + mt * 4096 + (((((sl) * 2) + aHalf) ^ l7) << 4)); }
#define LDBG(sl) { const unsigned char* _p = wfp + (sl) * 2048; \
    uint4 v0 = __ldg((const uint4*)(_p)); \
    uint4 v1 = __ldg((const uint4*)(_p + 512)); \
    uint4 v2 = __ldg((const uint4*)(_p + 1024)); \
    uint4 v3 = __ldg((const uint4*)(_p + 1536)); \
    bF[0][0]=v0.x; bF[0][1]=v0.y; bF[0][2]=v0.z; bF[0][3]=v0.w; \
    bF[1][0]=v1.x; bF[1][1]=v1.y; bF[1][2]=v1.z; bF[1][3]=v1.w; \
    bF[2][0]=v2.x; bF[2][1]=v2.y; bF[2][2]=v2.z; bF[2][3]=v2.w; \
    bF[3][0]=v3.x; bF[3][1]=v3.y; bF[3][2]=v3.z; bF[3][3]=v3.w; }
#define DOMMA() { _Pragma("unroll") for (int mt = 0; mt < 2; mt++) \
    _Pragma("unroll") for (int j = 0; j < 8; j++) \
        mma16816(acc[mt][j], aF[mt], bF[j >> 1][(j & 1) * 2], bF[j >> 1][(j & 1) * 2 + 1]); }

    for (int c = 0; c < NCHUNK; c++) {
        const int cur = c & 1;
        const int nxt = cur ^ 1;
        const uint32_t ycur = sb + SM_Y + cur * Y_STAGE;
        const unsigned char* wfp = g_wf + (size_t)c * 65536 + wn * 16384 + (lane << 4);
        const bool more = (c + 1 < NCHUNK);

        // 8 k16 slices; slice order skewed by warp row (phases 0/4);
        // the second CTA on the SM desyncs via its own barrier domain.
        #pragma unroll
        for (int ks = 0; ks < 8; ks++) {
            const int sl = (ks + 4 * wm) & 7;
            LDBG(sl);
            LDA(sl);
            DOMMA();
            if (ks == 0 && more) {   // warm L1 for next chunk's W frags
                #pragma unroll
                for (int t = 0; t < 2; t++)
                    asm volatile("prefetch.global.L1 [%0];"
                                 :: "l"(g_wf + (size_t)(c + 1) * 65536
                                        + (tid + t * NTH) * 128));
            }
            if (ks == 1 && more) buildLoad(c + 1, 0, yv);
            if (ks == 2 && more) buildStore(nxt, 0, yv);
            if (ks == 4 && more) buildLoad(c + 1, 1, yv);
            if (ks == 6 && more) buildStore(nxt, 1, yv);
        }
        __syncthreads();
    }
#undef LDA
#undef LDBG
#undef DOMMA

    // ---- epilogue: transpose via smem, coalesced stores ----
    float* buf = (float*)smem;                       // [64][72] fp32
    float* ob  = out + ((size_t)b * OUT_CH) * HW + hw0;
    #pragma unroll 1
    for (int slab = 0; slab < 4; slab++) {
        __syncthreads();
        if (wn == slab) {
            #pragma unroll
            for (int mt = 0; mt < 2; mt++)
                #pragma unroll
                for (int j = 0; j < 8; j++) {
                    int px = wm * 32 + mt * 16 + (lane >> 2);
                    int ch = j * 8 + (lane & 3) * 2;
                    buf[ch * 72 + px]           = acc[mt][j][0];
                    buf[(ch + 1) * 72 + px]     = acc[mt][j][1];
                    buf[ch * 72 + px + 8]       = acc[mt][j][2];
                    buf[(ch + 1) * 72 + px + 8] = acc[mt][j][3];
                }
        }
        __syncthreads();
        #pragma unroll
        for (int t = 0; t < 4; t++) {
            int e   = tid + t * NTH;                 // 0..1023
            int chl = e >> 4;
            int po  = (e & 15) << 2;
            float4 v = *(float4*)(buf + chl * 72 + po);
            *(float4*)(ob + (size_t)(slab * 64 + chl) * HW + po) = v;
        }
    }
}

// ---------------- launch ----------------
extern "C" void kernel_launch(void* const* d_in, const int* in_sizes, int n_in,
                              void* d_out, int out_size) {
    const float* x = (const float*)d_in[0];    // [B, 64, 64, 64] fp32
    const float* w = (const float*)d_in[1];    // [256, 2144] fp32
    float* out = (float*)d_out;                // [B, 256, 64, 64] fp32

    int pixels = in_sizes[0] / C_CH;           // B * 4096

    cudaFuncSetAttribute(quad_hmma_kernel,
                         cudaFuncAttributeMaxDynamicSharedMemorySize, SM_TOT);

    w_prep_kernel<<<272, 256>>>(w);
    quad_hmma_kernel<<<pixels / PX_CTA, NTH, SM_TOT>>>(x, out);
}

// round 15
// speedup vs baseline: 1.0655x; 1.0655x over previous
#include <cuda_runtime.h>
#include <cuda_fp16.h>
#include <cstdint>

#define C_CH     64
#define NIN      2144
#define NINP     2176        // padded to 34*64
#define OUT_CH   256
#define HW       4096
#define KC       64
#define NCHUNK   34
#define PX_CTA   64
#define NTH      256

// ---------------- prep storage (device globals) ----------------
// W per chunk: [chunk][n=256][128B row], SW128 pre-swizzled fp16, zero-padded.
#define WCHUNK_BYTES 32768
__device__ __align__(16) unsigned char g_w[NCHUNK * WCHUNK_BYTES];
__device__ __align__(16) uchar2 g_pairs[NINP];   // {i, j}; j==64 => constant-1 channel

// ---------------- smem layout (dynamic) ----------------
// XS : x tile [65 ch][64 px] fp32 (row 64 = 1.0f)  = 16640 B
// Y  : 2 stages x [64 px][128 B] fp16 SW128        = 2 x 8192 B
// W  : 2 stages x [256 n][128 B] fp16 SW128        = 2 x 32768 B
// PS : pair table 2176 uchar2                      =  4352 B
// Epilogue reuses [0, 18432) as fp32 [64][72] buffer.
#define SM_XS    0
#define SM_Y     16640
#define Y_STAGE  8192
#define SM_W     33024
#define W_STAGE  32768
#define SM_PS    98560
#define SM_TOT   102912

// ---------------- asm helpers ----------------
__device__ __forceinline__ void ldsm4(uint32_t (&r)[4], uint32_t addr) {
    asm volatile("ldmatrix.sync.aligned.m8n8.x4.shared.b16 {%0,%1,%2,%3}, [%4];"
                 : "=r"(r[0]), "=r"(r[1]), "=r"(r[2]), "=r"(r[3]) : "r"(addr));
}
__device__ __forceinline__ void mma16816(float (&c)[4], const uint32_t (&a)[4],
                                         uint32_t b0, uint32_t b1) {
    asm volatile(
        "mma.sync.aligned.m16n8k16.row.col.f32.f16.f16.f32 "
        "{%0,%1,%2,%3}, {%4,%5,%6,%7}, {%8,%9}, {%0,%1,%2,%3};"
        : "+f"(c[0]), "+f"(c[1]), "+f"(c[2]), "+f"(c[3])
        : "r"(a[0]), "r"(a[1]), "r"(a[2]), "r"(a[3]), "r"(b0), "r"(b1));
}
__device__ __forceinline__ void cp_async16(uint32_t saddr, const void* gptr) {
    asm volatile("cp.async.cg.shared.global [%0], [%1], 16;"
                 :: "r"(saddr), "l"(gptr) : "memory");
}

// ---------------- prep kernel: flat (chunk,row,kp) items, coalesced ----------------
// 34*256*32 = 278528 items; grid 1088 x 256. Lane-consecutive kp -> coalesced.
__global__ void w_prep_kernel(const float* __restrict__ w) {
    const int gid = blockIdx.x * 256 + threadIdx.x;

    if (blockIdx.x == 0) {           // pair table (redundant with chunk work; fine)
        int t = threadIdx.x;
        if (t < C_CH) {
            int i = t;
            g_pairs[i] = make_uchar2((unsigned char)i, 64);
            int base = C_CH + C_CH * i - (i * (i - 1)) / 2;
            for (int j = i; j < C_CH; j++)
                g_pairs[base + (j - i)] = make_uchar2((unsigned char)i, (unsigned char)j);
        }
        if (t >= 64 && t < 96)       // padding pairs (W is zero there)
            g_pairs[NIN + (t - 64)] = make_uchar2(0, 64);
    }

    const int kp = gid & 31;                 // 0..31 (2 k each)
    const int n  = (gid >> 5) & 255;         // output row
    const int c  = gid >> 13;                // chunk
    const int k  = c * KC + 2 * kp;

    const float* wr = w + (size_t)n * NIN;
    float f0 = (k     < NIN) ? wr[k]     : 0.0f;
    float f1 = (k + 1 < NIN) ? wr[k + 1] : 0.0f;
    __half2 h2 = __floats2half2_rn(f0, f1);
    int kl   = 2 * kp;
    int phys = (((kl >> 3) ^ (n & 7)) << 4) + (kl & 7) * 2;   // SW128
    *(uint32_t*)(g_w + (size_t)c * WCHUNK_BYTES + n * 128 + phys) = *(uint32_t*)&h2;
}

// ---------------- main kernel (identical to round-12 winner) ----------------
__global__ __launch_bounds__(NTH, 2)
void quad_hmma_kernel(const float* __restrict__ x, float* __restrict__ out) {
    extern __shared__ __align__(1024) unsigned char smem[];
    const int tid  = threadIdx.x;
    const int wid  = tid >> 5;
    const int lane = tid & 31;
    const int wm   = wid >> 2;          // warp row (M): 0..1, 32 px each (phase id)
    const int wn   = wid & 3;           // warp col (N): 0..3, 64 ch each
    const uint32_t sb = (uint32_t)__cvta_generic_to_shared(smem);

    float*  xs = (float*)(smem + SM_XS);
    uchar2* ps = (uchar2*)(smem + SM_PS);

    // ---- global pixel tile ----
    const int p0  = blockIdx.x * PX_CTA;
    const int b   = p0 >> 12;
    const int hw0 = p0 & 4095;
    const float* xb = x + (((size_t)b * C_CH) << 12) + hw0;

    // ---- load x tile: 64 ch x 64 px (1024 float4, 4/thread) + ones row ----
    #pragma unroll
    for (int t = 0; t < 4; t++) {
        int e  = tid + t * NTH;          // 0..1023
        int ch = e >> 4;                 // 16 float4 per 64-px row
        int po = (e & 15) << 2;
        *(float4*)(xs + ch * 64 + po) = *(const float4*)(xb + ((size_t)ch << 12) + po);
    }
    if (tid < 16) *(float4*)(xs + 64 * 64 + tid * 4) = make_float4(1.f, 1.f, 1.f, 1.f);
    #pragma unroll
    for (int t = 0; t < 2; t++) {
        int idx = tid + t * NTH;
        if (idx < NINP / 8) ((uint4*)ps)[idx] = ((const uint4*)g_pairs)[idx];
    }
    __syncthreads();

    // ---- per-lane swizzled ldmatrix row bases ----
    const uint32_t l7    = lane & 7;
    const uint32_t aRow  = (uint32_t)(wm * 32 + (lane & 15)) * 128;
    const uint32_t aHalf = (uint32_t)(lane >> 4);
    const uint32_t bRow  = (uint32_t)(wn * 64 + ((lane >> 4) << 3) + (lane & 7)) * 128;
    const uint32_t bHalf = (uint32_t)((lane >> 3) & 1);

    float acc[2][8][4];
    #pragma unroll
    for (int mt = 0; mt < 2; mt++)
        #pragma unroll
        for (int j = 0; j < 8; j++)
            #pragma unroll
            for (int q = 0; q < 4; q++) acc[mt][j][q] = 0.0f;

    const int pY  = tid & 63;           // pixel this thread builds
    const int q16 = tid >> 6;           // which 16-k group (0..3)
    const float* xcol = xs + pY;

    // ---- copy W chunk (linear; g_w pre-swizzled) : 2048 uint4, 8/thread ----
    auto copyW = [&](int cc, int stage) {
        const unsigned char* src = g_w + (size_t)cc * WCHUNK_BYTES;
        uint32_t dst = sb + SM_W + stage * W_STAGE;
        #pragma unroll
        for (int t = 0; t < 8; t++) {
            uint32_t off = (uint32_t)(tid + t * NTH) * 16;
            cp_async16(dst + off, src + off);
        }
        asm volatile("cp.async.commit_group;" ::: "memory");
    };

    // ---- build Y: load phase (16 pairs -> 8 packed half2) ----
    auto buildLoad = [&](int cc, uint32_t* yv) {
        const uint4* pp = (const uint4*)((const unsigned char*)ps + cc * 128 + q16 * 32);
        uint4 P0 = pp[0], P1 = pp[1];
        uint32_t wsrc[8] = {P0.x, P0.y, P0.z, P0.w, P1.x, P1.y, P1.z, P1.w};
        #pragma unroll
        for (int q = 0; q < 8; q++) {
            uint32_t w_ = wsrc[q];
            float a0 = xcol[(w_ & 255u) << 6];
            float b0 = xcol[((w_ >> 8) & 255u) << 6];
            float a1 = xcol[((w_ >> 16) & 255u) << 6];
            float b1 = xcol[(w_ >> 24) << 6];
            __half2 h = __float22half2_rn(make_float2(a0 * b0, a1 * b1));
            yv[q] = *(uint32_t*)&h;
        }
    };
    // ---- build Y: store phase (2 x STS.128, SW128) ----
    auto buildStore = [&](int stage, const uint32_t* yv) {
        unsigned char* yb = smem + SM_Y + stage * Y_STAGE + pY * 128;
        uint32_t s0 = (uint32_t)(((q16 * 2)     ^ (pY & 7)) << 4);
        uint32_t s1 = (uint32_t)(((q16 * 2 + 1) ^ (pY & 7)) << 4);
        *(uint4*)(yb + s0) = make_uint4(yv[0], yv[1], yv[2], yv[3]);
        *(uint4*)(yb + s1) = make_uint4(yv[4], yv[5], yv[6], yv[7]);
    };

    // ---- prologue: stage 0 ----
    copyW(0, 0);
    {
        uint32_t yv0[8];
        buildLoad(0, yv0);
        buildStore(0, yv0);
    }
    asm volatile("cp.async.wait_group 0;" ::: "memory");
    __syncthreads();

    uint32_t aF[2][4], bF[4][4], yv[8];

#define LDA(sl) { _Pragma("unroll") for (int mt = 0; mt < 2; mt++) \
    ldsm4(aF[mt], ycur + aRow + mt * 2048 + (((((sl) * 2) + aHalf) ^ l7) << 4)); }
#define LDB(sl) { _Pragma("unroll") for (int nt = 0; nt < 4; nt++) \
    ldsm4(bF[nt], wcur + bRow + nt * 2048 + (((((sl) * 2) + bHalf) ^ l7) << 4)); }
#define DOMMA() { _Pragma("unroll") for (int mt = 0; mt < 2; mt++) \
    _Pragma("unroll") for (int j = 0; j < 8; j++) \
        mma16816(acc[mt][j], aF[mt], bF[j >> 1][(j & 1) * 2], bF[j >> 1][(j & 1) * 2 + 1]); }

    for (int c = 0; c < NCHUNK; c++) {
        const int cur = c & 1;
        const int nxt = cur ^ 1;
        const uint32_t ycur = sb + SM_Y + cur * Y_STAGE;
        const uint32_t wcur = sb + SM_W + cur * W_STAGE;
        const bool more = (c + 1 < NCHUNK);

        // Slice order skewed by warp row; the second CTA on the SM is
        // desynchronized by its independent barrier domain.
        #pragma unroll
        for (int ks = 0; ks < 4; ks++) {
            const int sl = (ks + 2 * wm) & 3;
            LDA(sl); LDB(sl);
            DOMMA();
            if (ks == 0 && more) copyW(c + 1, nxt);
            if (ks == 1 && more) buildLoad(c + 1, yv);
            if (ks == 3 && more) buildStore(nxt, yv);
        }

        asm volatile("cp.async.wait_group 0;" ::: "memory");
        __syncthreads();
    }
#undef LDA
#undef LDB
#undef DOMMA

    // ---- epilogue: transpose via smem, coalesced stores ----
    float* buf = (float*)smem;                       // [64][72] fp32
    float* ob  = out + ((size_t)b * OUT_CH) * HW + hw0;
    #pragma unroll 1
    for (int slab = 0; slab < 4; slab++) {
        __syncthreads();
        if (wn == slab) {
            #pragma unroll
            for (int mt = 0; mt < 2; mt++)
                #pragma unroll
                for (int j = 0; j < 8; j++) {
                    int px = wm * 32 + mt * 16 + (lane >> 2);
                    int ch = j * 8 + (lane & 3) * 2;
                    buf[ch * 72 + px]           = acc[mt][j][0];
                    buf[(ch + 1) * 72 + px]     = acc[mt][j][1];
                    buf[ch * 72 + px + 8]       = acc[mt][j][2];
                    buf[(ch + 1) * 72 + px + 8] = acc[mt][j][3];
                }
        }
        __syncthreads();
        #pragma unroll
        for (int t = 0; t < 4; t++) {
            int e   = tid + t * NTH;                 // 0..1023
            int chl = e >> 4;
            int po  = (e & 15) << 2;
            float4 v = *(float4*)(buf + chl * 72 + po);
            *(float4*)(ob + (size_t)(slab * 64 + chl) * HW + po) = v;
        }
    }
}

// ---------------- launch ----------------
extern "C" void kernel_launch(void* const* d_in, const int* in_sizes, int n_in,
                              void* d_out, int out_size) {
    const float* x = (const float*)d_in[0];    // [B, 64, 64, 64] fp32
    const float* w = (const float*)d_in[1];    // [256, 2144] fp32
    float* out = (float*)d_out;                // [B, 256, 64, 64] fp32

    int pixels = in_sizes[0] / C_CH;           // B * 4096

    cudaFuncSetAttribute(quad_hmma_kernel,
                         cudaFuncAttributeMaxDynamicSharedMemorySize, SM_TOT);

    w_prep_kernel<<<1088, 256>>>(w);
    quad_hmma_kernel<<<pixels / PX_CTA, NTH, SM_TOT>>>(x, out);
}